// round 6
// baseline (speedup 1.0000x reference)
#include <cuda_runtime.h>
#include <cuda_bf16.h>
#include <cstdint>

// Problem constants (fixed shapes from reference setup_inputs)
#define N 384
#define D 512
#define MARGIN 1.0f
#define NBLK 384

// Scratch: device globals (no allocation allowed)
__device__ float g_G[N * N];        // Gram matrix X @ X^T (fp32)
__device__ float g_sq[N];           // fp32 row sums of x*x
__device__ float g_asum[N];         // per-anchor triplet loss sum
__device__ int   g_acnt[N];         // per-anchor valid-triple count

// Sync state (integer only; epoch is monotone across graph replays,
// count/ticket self-reset each launch -> deterministic, replay-safe)
__device__ unsigned g_count  = 0;
__device__ unsigned g_epoch  = 0;
__device__ unsigned g_ticket = 0;

__device__ __forceinline__ void grid_barrier() {
    __syncthreads();
    if (threadIdx.x == 0) {
        unsigned e = *(volatile unsigned*)&g_epoch;
        __threadfence();
        if (atomicAdd(&g_count, 1u) == NBLK - 1) {
            g_count = 0;
            __threadfence();
            *(volatile unsigned*)&g_epoch = e + 1;   // release
        } else {
            while (*(volatile unsigned*)&g_epoch == e) { __nanosleep(64); }
        }
        __threadfence();
    }
    __syncthreads();
}

// ---------------------------------------------------------------------------
// Single fused kernel, 384 blocks x 256 threads, all co-resident
// (launch_bounds(256,4): regs<=64, smem 8.8KB -> >=4 blocks/SM -> 592 >= 384).
//
// Phase 1:
//   blocks   0..143 : G = X @ X^T, 32x32 tiles, 2x2 register tile, k-major
//                     smem with float2 LDS (FFMA-throughput bound)
//   blocks 144..335 : g_sq rows (2 rows per block, fp32, deterministic)
//   blocks 336..383 : idle
// grid barrier
// Phase 2: block a = anchor a: distance row, ballot compaction, pair hinge
//          sum, deterministic tree reduce -> g_asum/g_acnt
// Last-ticket block: deterministic final reduction + divide -> out[0]
// ---------------------------------------------------------------------------
__global__ void __launch_bounds__(256, 4)
fused_triplet_kernel(const float* __restrict__ X,
                     const int*   __restrict__ labels,
                     float*       __restrict__ out) {
    __shared__ float pool[2 * 32 * 34];   // 2176 floats = 8704 B (phase1/2 union)
    __shared__ int   s_np, s_nn, s_last;

    const int b   = blockIdx.x;
    const int tid = threadIdx.x;

    // ---------------- Phase 1 ----------------
    if (b < 144) {
        // Gram tile: rows [row0,row0+32), cols [col0,col0+32)
        float (*At)[34] = (float(*)[34])pool;              // k-major: At[k][r]
        float (*Bt)[34] = (float(*)[34])(pool + 32 * 34);
        const int bx = b % 12, by = b / 12;
        const int row0 = by * 32, col0 = bx * 32;
        const int ty = tid >> 4;          // 0..15 (row pair)
        const int tx = tid & 15;          // 0..15 (col pair)

        float a00 = 0.f, a01 = 0.f, a10 = 0.f, a11 = 0.f;

        for (int k0 = 0; k0 < D; k0 += 32) {
#pragma unroll
            for (int i = 0; i < 4; i++) {
                int idx = i * 256 + tid;
                int r = idx >> 5, k = idx & 31;          // coalesced gmem reads
                At[k][r] = X[(row0 + r) * D + k0 + k];
                Bt[k][r] = X[(col0 + r) * D + k0 + k];
            }
            __syncthreads();
#pragma unroll
            for (int k = 0; k < 32; k++) {
                float2 av = *(const float2*)&At[k][2 * ty];  // broadcast (2 addrs/warp)
                float2 bv = *(const float2*)&Bt[k][2 * tx];  // conflict-free 128B
                a00 = fmaf(av.x, bv.x, a00);
                a01 = fmaf(av.x, bv.y, a01);
                a10 = fmaf(av.y, bv.x, a10);
                a11 = fmaf(av.y, bv.y, a11);
            }
            __syncthreads();
        }
        *(float2*)&g_G[(row0 + 2 * ty)     * N + col0 + 2 * tx] = make_float2(a00, a01);
        *(float2*)&g_G[(row0 + 2 * ty + 1) * N + col0 + 2 * tx] = make_float2(a10, a11);
    } else if (b < 336) {
        // Squared row norms: 2 rows per block, 128 threads each
        const int half = tid >> 7;                 // 0/1
        const int lane = tid & 127;
        const int row  = (b - 144) * 2 + half;
        const float* xr = X + row * D;
        float s = 0.0f;
#pragma unroll
        for (int i = 0; i < D / 128; i++) {
            float v = xr[lane + i * 128];
            s = fmaf(v, v, s);
        }
        float* red = pool + half * 128;
        red[lane] = s;
        __syncthreads();
#pragma unroll
        for (int st = 64; st > 0; st >>= 1) {
            if (lane < st) red[lane] += red[lane + st];
            __syncthreads();
        }
        if (lane == 0) g_sq[row] = red[0];
    }

    grid_barrier();

    // ---------------- Phase 2: anchor = blockIdx.x ----------------
    {
        float* dr  = pool;            // [384]
        float* pd  = pool + 384;      // [384]
        float* nd  = pool + 768;      // [384]
        float* red = pool + 1152;     // [256]

        const int a   = b;
        const float sqa = g_sq[a];
        const int la  = labels[a];

        // distance row: d = sqrt(max(sq[a]+sq[b]-2*G[a,b], 0))
        for (int j = tid; j < N; j += 256) {
            float d2 = sqa + g_sq[j] - 2.0f * g_G[a * N + j];
            dr[j] = sqrtf(fmaxf(d2, 0.0f));
        }
        __syncthreads();

        // warp 0: deterministic (index-ordered) compaction
        if (tid < 32) {
            int npos = 0, nneg = 0;
#pragma unroll
            for (int c = 0; c < N / 32; c++) {
                int j = c * 32 + tid;
                bool isp = (labels[j] == la);
                unsigned m = __ballot_sync(0xffffffffu, isp);
                int below_pos = __popc(m & ((1u << tid) - 1u));
                float d = dr[j];
                if (isp) pd[npos + below_pos] = d;
                else     nd[nneg + (tid - below_pos)] = d;
                int p = __popc(m);
                npos += p;
                nneg += 32 - p;
            }
            if (tid == 0) { s_np = npos; s_nn = nneg; }
        }
        __syncthreads();

        const int np = s_np;
        const int nn = s_nn;
        const int total = np * nn;

        float acc = 0.0f;
        for (int i = tid; i < total; i += 256) {
            int p = i / nn;
            int n = i - p * nn;
            acc += fmaxf(pd[p] - nd[n] + MARGIN, 0.0f);
        }
        red[tid] = acc;
        __syncthreads();
#pragma unroll
        for (int s = 128; s > 0; s >>= 1) {
            if (tid < s) red[tid] += red[tid + s];
            __syncthreads();
        }
        if (tid == 0) {
            g_asum[a] = red[0];
            g_acnt[a] = total;
        }
    }

    // ---------------- Finalize: last block by ticket ----------------
    __syncthreads();
    if (tid == 0) {
        __threadfence();
        unsigned t = atomicAdd(&g_ticket, 1u);
        s_last = (t == NBLK - 1) ? 1 : 0;
    }
    __syncthreads();

    if (s_last) {
        if (tid == 0) g_ticket = 0;      // reset for next replay
        __threadfence();                  // acquire: see all g_asum/g_acnt

        float* rs = pool;                 // [256]
        int*   rc = (int*)(pool + 256);   // [256]
        float s = 0.0f;
        int   c = 0;
        for (int i = tid; i < N; i += 256) {  // fixed order -> deterministic
            s += g_asum[i];
            c += g_acnt[i];
        }
        rs[tid] = s;
        rc[tid] = c;
        __syncthreads();
#pragma unroll
        for (int st = 128; st > 0; st >>= 1) {
            if (tid < st) { rs[tid] += rs[tid + st]; rc[tid] += rc[tid + st]; }
            __syncthreads();
        }
        if (tid == 0) {
            out[0] = rs[0] / ((float)rc[0] + 1e-16f);
        }
    }
}

// ---------------------------------------------------------------------------
extern "C" void kernel_launch(void* const* d_in, const int* in_sizes, int n_in,
                              void* d_out, int out_size) {
    const float* X      = (const float*)d_in[0];
    const int*   labels = (const int*)d_in[1];
    float*       out    = (float*)d_out;

    fused_triplet_kernel<<<NBLK, 256>>>(X, labels, out);
}

// round 9
// speedup vs baseline: 1.4055x; 1.4055x over previous
#include <cuda_runtime.h>
#include <cuda_bf16.h>
#include <cstdint>

// Problem constants (fixed shapes from reference setup_inputs)
#define N 384
#define D 512
#define MARGIN 1.0f
#define NBLK 384
#define KSLICES 4
#define KS (D / KSLICES)          // 128 k per slice
#define TILES 6                   // 6x6 tiles of 64x64

// Scratch: device globals (no allocation allowed)
__device__ float g_Gp[KSLICES][N * N];  // split-K Gram partials
__device__ float g_sq[N];               // fp32 row sums of x*x
__device__ float g_asum[N];             // per-anchor triplet loss sum
__device__ int   g_acnt[N];             // per-anchor valid-triple count

// Sync state (integer only; epoch monotone across graph replays,
// count/ticket self-reset each launch -> deterministic, replay-safe)
__device__ unsigned g_count  = 0;
__device__ unsigned g_epoch  = 0;
__device__ unsigned g_ticket = 0;

__device__ __forceinline__ void grid_barrier() {
    __syncthreads();
    if (threadIdx.x == 0) {
        unsigned e = *(volatile unsigned*)&g_epoch;
        __threadfence();
        if (atomicAdd(&g_count, 1u) == NBLK - 1) {
            g_count = 0;
            __threadfence();
            *(volatile unsigned*)&g_epoch = e + 1;   // release
        } else {
            while (*(volatile unsigned*)&g_epoch == e) { __nanosleep(32); }
        }
        __threadfence();
    }
    __syncthreads();
}

// Row-major tile: 32 floats (128B) per row, XOR chunk swizzle.
// r = row 0..63, c = 16B chunk 0..7. Returns float offset.
__device__ __forceinline__ int SW(int r, int c) {
    return r * 32 + ((c ^ ((r >> 2) & 7)) << 2);
}

// ---------------------------------------------------------------------------
// Single fused kernel, 384 blocks x 256 threads, all co-resident
// (launch_bounds(256,3): 444 slots >= 384 -> grid barrier is safe).
//
// Phase 1:
//   blocks   0..143 : split-K Gram. block = kslice*36 + tile (6x6 of 64x64).
//                     Row-major swizzled smem (all STS.128/LDS.128,
//                     conflict-free), 4x4 micro-tile with dot-4 inner step:
//                     64 FFMA per 8 LDS.128 -> FFMA-throughput bound.
//   blocks 144..335 : g_sq rows (2 rows per block, fp32, deterministic)
//   blocks 336..383 : idle
// grid barrier
// Phase 2: block a = anchor a: distance row from fixed-order sum of the 4
//          partials, ballot compaction, hinge pair sum, tree reduce.
// Last-ticket block: deterministic final reduction + divide -> out[0]
// ---------------------------------------------------------------------------
__global__ void __launch_bounds__(256, 3)
fused_triplet_kernel(const float* __restrict__ X,
                     const int*   __restrict__ labels,
                     float*       __restrict__ out) {
    __shared__ float pool[4096];      // As[64*32] + Bs[64*32] = 16KB (phase union)
    __shared__ int   s_np, s_nn, s_last;

    const int b   = blockIdx.x;
    const int tid = threadIdx.x;

    // ---------------- Phase 1 ----------------
    if (b < KSLICES * 36) {
        float* As = pool;                 // [64][32] swizzled
        float* Bs = pool + 2048;
        const int kslice = b / 36;
        const int t      = b % 36;
        const int row0 = (t / TILES) * 64;
        const int col0 = (t % TILES) * 64;
        const int kbase = kslice * KS;

        const int tx = tid & 15;          // 0..15 (col quad)
        const int ty = tid >> 4;          // 0..15 (row quad)
        const int swA = ty & 7;           // swizzle key for av rows (4ty+i)>>2 = ty
        const int swB = tx & 7;

        float acc[4][4];
#pragma unroll
        for (int i = 0; i < 4; i++)
#pragma unroll
            for (int j = 0; j < 4; j++) acc[i][j] = 0.f;

        const int lr = tid >> 3;          // 0..31: row for loads
        const int kg = tid & 7;           // 0..7: 16B chunk

        for (int c = 0; c < KS / 32; c++) {           // 4 chunks of 32 k
            const int k0 = kbase + c * 32;
#pragma unroll
            for (int h = 0; h < 2; h++) {
                int r = lr + h * 32;
                float4 va = *(const float4*)&X[(row0 + r) * D + k0 + kg * 4];
                float4 vb = *(const float4*)&X[(col0 + r) * D + k0 + kg * 4];
                *(float4*)&As[SW(r, kg)] = va;        // STS.128, conflict-free
                *(float4*)&Bs[SW(r, kg)] = vb;
            }
            __syncthreads();
#pragma unroll
            for (int kc = 0; kc < 8; kc++) {          // 4 k per step
                float4 av[4], bv[4];
#pragma unroll
                for (int i = 0; i < 4; i++)
                    av[i] = *(const float4*)&As[(4 * ty + i) * 32 + ((kc ^ swA) << 2)];
#pragma unroll
                for (int j = 0; j < 4; j++)
                    bv[j] = *(const float4*)&Bs[(4 * tx + j) * 32 + ((kc ^ swB) << 2)];
#pragma unroll
                for (int i = 0; i < 4; i++)
#pragma unroll
                    for (int j = 0; j < 4; j++) {
                        acc[i][j] = fmaf(av[i].x, bv[j].x, acc[i][j]);
                        acc[i][j] = fmaf(av[i].y, bv[j].y, acc[i][j]);
                        acc[i][j] = fmaf(av[i].z, bv[j].z, acc[i][j]);
                        acc[i][j] = fmaf(av[i].w, bv[j].w, acc[i][j]);
                    }
            }
            __syncthreads();
        }
        float* Gp = g_Gp[kslice];
#pragma unroll
        for (int i = 0; i < 4; i++) {
            *(float4*)&Gp[(row0 + 4 * ty + i) * N + col0 + 4 * tx] =
                make_float4(acc[i][0], acc[i][1], acc[i][2], acc[i][3]);
        }
    } else if (b < 336) {
        // Squared row norms: 2 rows per block, 128 threads each
        const int half = tid >> 7;                 // 0/1
        const int lane = tid & 127;
        const int row  = (b - 144) * 2 + half;
        const float* xr = X + row * D;
        float s = 0.0f;
#pragma unroll
        for (int i = 0; i < D / 128; i++) {
            float v = xr[lane + i * 128];
            s = fmaf(v, v, s);
        }
        float* red = pool + half * 128;
        red[lane] = s;
        __syncthreads();
#pragma unroll
        for (int st = 64; st > 0; st >>= 1) {
            if (lane < st) red[lane] += red[lane + st];
            __syncthreads();
        }
        if (lane == 0) g_sq[row] = red[0];
    }

    grid_barrier();

    // ---------------- Phase 2: anchor = blockIdx.x ----------------
    {
        float* dr  = pool;            // [384]
        float* pd  = pool + 384;      // [384]
        float* nd  = pool + 768;      // [384]
        float* red = pool + 1152;     // [256]

        const int a = b;
        const float sqa = g_sq[a];
        const int la  = labels[a];

        // distance row: fixed-order split-K combine, then safe sqrt
        for (int j = tid; j < N; j += 256) {
            float g = ((g_Gp[0][a * N + j] + g_Gp[1][a * N + j])
                      + g_Gp[2][a * N + j]) + g_Gp[3][a * N + j];
            float d2 = sqa + g_sq[j] - 2.0f * g;
            dr[j] = sqrtf(fmaxf(d2, 0.0f));
        }
        __syncthreads();

        // warp 0: deterministic (index-ordered) compaction
        if (tid < 32) {
            int npos = 0, nneg = 0;
#pragma unroll
            for (int c = 0; c < N / 32; c++) {
                int j = c * 32 + tid;
                bool isp = (labels[j] == la);
                unsigned m = __ballot_sync(0xffffffffu, isp);
                int below_pos = __popc(m & ((1u << tid) - 1u));
                float d = dr[j];
                if (isp) pd[npos + below_pos] = d;
                else     nd[nneg + (tid - below_pos)] = d;
                int p = __popc(m);
                npos += p;
                nneg += 32 - p;
            }
            if (tid == 0) { s_np = npos; s_nn = nneg; }
        }
        __syncthreads();

        const int np = s_np;
        const int nn = s_nn;
        const int total = np * nn;

        float acc = 0.0f;
        if (total > 0) {
            int p = tid / nn;                 // one division only
            int n = tid - p * nn;
            for (int i = tid; i < total; i += 256) {
                acc += fmaxf(pd[p] - nd[n] + MARGIN, 0.0f);
                n += 256;
                while (n >= nn) { n -= nn; p++; }   // incremental carry
            }
        }
        red[tid] = acc;
        __syncthreads();
#pragma unroll
        for (int s = 128; s > 0; s >>= 1) {
            if (tid < s) red[tid] += red[tid + s];
            __syncthreads();
        }
        if (tid == 0) {
            g_asum[a] = red[0];
            g_acnt[a] = total;
        }
    }

    // ---------------- Finalize: last block by ticket ----------------
    __syncthreads();
    if (tid == 0) {
        __threadfence();
        unsigned t = atomicAdd(&g_ticket, 1u);
        s_last = (t == NBLK - 1) ? 1 : 0;
    }
    __syncthreads();

    if (s_last) {
        if (tid == 0) g_ticket = 0;      // reset for next replay
        __threadfence();                  // acquire: see all g_asum/g_acnt

        float* rs = pool;                 // [256]
        int*   rc = (int*)(pool + 256);   // [256]
        float s = 0.0f;
        int   c = 0;
        for (int i = tid; i < N; i += 256) {  // fixed order -> deterministic
            s += g_asum[i];
            c += g_acnt[i];
        }
        rs[tid] = s;
        rc[tid] = c;
        __syncthreads();
#pragma unroll
        for (int st = 128; st > 0; st >>= 1) {
            if (tid < st) { rs[tid] += rs[tid + st]; rc[tid] += rc[tid + st]; }
            __syncthreads();
        }
        if (tid == 0) {
            out[0] = rs[0] / ((float)rc[0] + 1e-16f);
        }
    }
}

// ---------------------------------------------------------------------------
extern "C" void kernel_launch(void* const* d_in, const int* in_sizes, int n_in,
                              void* d_out, int out_size) {
    const float* X      = (const float*)d_in[0];
    const int*   labels = (const int*)d_in[1];
    float*       out    = (float*)d_out;

    fused_triplet_kernel<<<NBLK, 256>>>(X, labels, out);
}

// round 10
// speedup vs baseline: 1.4250x; 1.0139x over previous
#include <cuda_runtime.h>
#include <cuda_bf16.h>
#include <cstdint>

// Problem constants (fixed shapes from reference setup_inputs)
#define N 384
#define D 512
#define MARGIN 1.0f
#define NBLK 384
#define KSLICES 8
#define KS (D / KSLICES)          // 64 k per slice
#define TILES 6                   // 6x6 tiles of 64x64

// Scratch: device globals (no allocation allowed)
__device__ float g_Gp[KSLICES][N * N];  // split-K Gram partials
__device__ float g_sq[N];               // fp32 row sums of x*x
__device__ float g_asum[N];             // per-anchor triplet loss sum
__device__ int   g_acnt[N];             // per-anchor valid-triple count

// Sync state (integer only; epoch monotone across graph replays,
// count/ticket self-reset each launch -> deterministic, replay-safe)
__device__ unsigned g_count  = 0;
__device__ unsigned g_epoch  = 0;
__device__ unsigned g_ticket = 0;

__device__ __forceinline__ void grid_barrier() {
    __syncthreads();
    if (threadIdx.x == 0) {
        unsigned e = *(volatile unsigned*)&g_epoch;
        __threadfence();
        if (atomicAdd(&g_count, 1u) == NBLK - 1) {
            g_count = 0;
            __threadfence();
            *(volatile unsigned*)&g_epoch = e + 1;   // release
        } else {
            while (*(volatile unsigned*)&g_epoch == e) { __nanosleep(64); }
        }
        __threadfence();
    }
    __syncthreads();
}

// Row-major tile: 32 floats (128B) per row, XOR chunk swizzle.
__device__ __forceinline__ int SW(int r, int c) {
    return r * 32 + ((c ^ ((r >> 2) & 7)) << 2);
}

// ---------------------------------------------------------------------------
// Single fused kernel, 384 blocks x 256 threads, all co-resident
// (launch_bounds(256,3): 444 slots >= 384 -> grid barrier safe).
//
// Phase 1:
//   blocks   0..287 : split-K Gram, 8 k-slices x 36 tiles (64x64).
//                     ~2 gram blocks/SM -> 16 FFMA warps/SM for latency hiding.
//                     Register prefetch of next chunk's LDG overlaps L2 latency
//                     with compute. All smem traffic is STS.128/LDS.128,
//                     conflict-free via XOR swizzle.
//   blocks 288..383 : g_sq rows (4 rows per block, fp32, deterministic)
// grid barrier
// Phase 2: block a = anchor a: distance row from fixed-order sum of the 8
//          partials, ballot compaction, hinge pair sum, tree reduce.
// Last-ticket block: deterministic final reduction + divide -> out[0]
// ---------------------------------------------------------------------------
__global__ void __launch_bounds__(256, 3)
fused_triplet_kernel(const float* __restrict__ X,
                     const int*   __restrict__ labels,
                     float*       __restrict__ out) {
    __shared__ float pool[4096];      // As[64*32] + Bs[64*32] = 16KB (phase union)
    __shared__ int   s_np, s_nn, s_last;

    const int b   = blockIdx.x;
    const int tid = threadIdx.x;

    // ---------------- Phase 1 ----------------
    if (b < KSLICES * 36) {
        float* As = pool;                 // [64][32] swizzled
        float* Bs = pool + 2048;
        const int kslice = b / 36;
        const int t      = b % 36;
        const int row0 = (t / TILES) * 64;
        const int col0 = (t % TILES) * 64;
        const int kbase = kslice * KS;

        const int tx = tid & 15;          // 0..15 (col quad)
        const int ty = tid >> 4;          // 0..15 (row quad)
        const int swA = ty & 7;
        const int swB = tx & 7;

        float acc[4][4];
#pragma unroll
        for (int i = 0; i < 4; i++)
#pragma unroll
            for (int j = 0; j < 4; j++) acc[i][j] = 0.f;

        const int lr = tid >> 3;          // 0..31: row for loads
        const int kg = tid & 7;           // 0..7: 16B chunk

        // prefetch chunk 0 into registers
        float4 va0, va1, vb0, vb1;
        {
            const int k0 = kbase;
            va0 = *(const float4*)&X[(row0 + lr)      * D + k0 + kg * 4];
            vb0 = *(const float4*)&X[(col0 + lr)      * D + k0 + kg * 4];
            va1 = *(const float4*)&X[(row0 + lr + 32) * D + k0 + kg * 4];
            vb1 = *(const float4*)&X[(col0 + lr + 32) * D + k0 + kg * 4];
        }

#pragma unroll
        for (int c = 0; c < KS / 32; c++) {           // 2 chunks of 32 k
            // store prefetched chunk to smem
            *(float4*)&As[SW(lr,      kg)] = va0;
            *(float4*)&Bs[SW(lr,      kg)] = vb0;
            *(float4*)&As[SW(lr + 32, kg)] = va1;
            *(float4*)&Bs[SW(lr + 32, kg)] = vb1;
            __syncthreads();

            // prefetch next chunk (LDG in flight during compute)
            if (c + 1 < KS / 32) {
                const int k0 = kbase + (c + 1) * 32;
                va0 = *(const float4*)&X[(row0 + lr)      * D + k0 + kg * 4];
                vb0 = *(const float4*)&X[(col0 + lr)      * D + k0 + kg * 4];
                va1 = *(const float4*)&X[(row0 + lr + 32) * D + k0 + kg * 4];
                vb1 = *(const float4*)&X[(col0 + lr + 32) * D + k0 + kg * 4];
            }

#pragma unroll
            for (int kc = 0; kc < 8; kc++) {          // 4 k per step
                float4 av[4], bv[4];
#pragma unroll
                for (int i = 0; i < 4; i++)
                    av[i] = *(const float4*)&As[(4 * ty + i) * 32 + ((kc ^ swA) << 2)];
#pragma unroll
                for (int j = 0; j < 4; j++)
                    bv[j] = *(const float4*)&Bs[(4 * tx + j) * 32 + ((kc ^ swB) << 2)];
#pragma unroll
                for (int i = 0; i < 4; i++)
#pragma unroll
                    for (int j = 0; j < 4; j++) {
                        acc[i][j] = fmaf(av[i].x, bv[j].x, acc[i][j]);
                        acc[i][j] = fmaf(av[i].y, bv[j].y, acc[i][j]);
                        acc[i][j] = fmaf(av[i].z, bv[j].z, acc[i][j]);
                        acc[i][j] = fmaf(av[i].w, bv[j].w, acc[i][j]);
                    }
            }
            __syncthreads();
        }
        float* Gp = g_Gp[kslice];
#pragma unroll
        for (int i = 0; i < 4; i++) {
            *(float4*)&Gp[(row0 + 4 * ty + i) * N + col0 + 4 * tx] =
                make_float4(acc[i][0], acc[i][1], acc[i][2], acc[i][3]);
        }
    } else {
        // Squared row norms: 4 rows per block, 64 threads each
        const int quad = tid >> 6;                 // 0..3
        const int lane = tid & 63;
        const int row  = (b - KSLICES * 36) * 4 + quad;
        const float* xr = X + row * D;
        float s = 0.0f;
#pragma unroll
        for (int i = 0; i < D / 64; i++) {
            float v = xr[lane + i * 64];
            s = fmaf(v, v, s);
        }
        float* red = pool + quad * 64;
        red[lane] = s;
        __syncthreads();
#pragma unroll
        for (int st = 32; st > 0; st >>= 1) {
            if (lane < st) red[lane] += red[lane + st];
            __syncthreads();
        }
        if (lane == 0) g_sq[row] = red[0];
    }

    grid_barrier();

    // ---------------- Phase 2: anchor = blockIdx.x ----------------
    {
        float* dr  = pool;            // [384]
        float* pd  = pool + 384;      // [384]
        float* nd  = pool + 768;      // [384]
        float* red = pool + 1152;     // [256]

        const int a = b;
        const float sqa = g_sq[a];
        const int la  = labels[a];

        // distance row: fixed-order split-K combine, then safe sqrt
        for (int j = tid; j < N; j += 256) {
            float g = g_Gp[0][a * N + j];
#pragma unroll
            for (int s = 1; s < KSLICES; s++) g += g_Gp[s][a * N + j];
            float d2 = sqa + g_sq[j] - 2.0f * g;
            dr[j] = sqrtf(fmaxf(d2, 0.0f));
        }
        __syncthreads();

        // warp 0: deterministic (index-ordered) compaction
        if (tid < 32) {
            int npos = 0, nneg = 0;
#pragma unroll
            for (int c = 0; c < N / 32; c++) {
                int j = c * 32 + tid;
                bool isp = (labels[j] == la);
                unsigned m = __ballot_sync(0xffffffffu, isp);
                int below_pos = __popc(m & ((1u << tid) - 1u));
                float d = dr[j];
                if (isp) pd[npos + below_pos] = d;
                else     nd[nneg + (tid - below_pos)] = d;
                int p = __popc(m);
                npos += p;
                nneg += 32 - p;
            }
            if (tid == 0) { s_np = npos; s_nn = nneg; }
        }
        __syncthreads();

        const int np = s_np;
        const int nn = s_nn;

        // hinge pair sum: p outer (broadcast LDS), n strided (sequential LDS)
        float acc = 0.0f;
        for (int p = 0; p < np; p++) {
            const float dpm = pd[p] + MARGIN;
            for (int n = tid; n < nn; n += 256)
                acc += fmaxf(dpm - nd[n], 0.0f);
        }
        red[tid] = acc;
        __syncthreads();
#pragma unroll
        for (int s = 128; s > 0; s >>= 1) {
            if (tid < s) red[tid] += red[tid + s];
            __syncthreads();
        }
        if (tid == 0) {
            g_asum[a] = red[0];
            g_acnt[a] = np * nn;
        }
    }

    // ---------------- Finalize: last block by ticket ----------------
    __syncthreads();
    if (tid == 0) {
        __threadfence();
        unsigned t = atomicAdd(&g_ticket, 1u);
        s_last = (t == NBLK - 1) ? 1 : 0;
    }
    __syncthreads();

    if (s_last) {
        if (tid == 0) g_ticket = 0;      // reset for next replay
        __threadfence();                  // acquire: see all g_asum/g_acnt

        float* rs = pool;                 // [256]
        int*   rc = (int*)(pool + 256);   // [256]
        float s = 0.0f;
        int   c = 0;
        for (int i = tid; i < N; i += 256) {  // fixed order -> deterministic
            s += g_asum[i];
            c += g_acnt[i];
        }
        rs[tid] = s;
        rc[tid] = c;
        __syncthreads();
#pragma unroll
        for (int st = 128; st > 0; st >>= 1) {
            if (tid < st) { rs[tid] += rs[tid + st]; rc[tid] += rc[tid + st]; }
            __syncthreads();
        }
        if (tid == 0) {
            out[0] = rs[0] / ((float)rc[0] + 1e-16f);
        }
    }
}

// ---------------------------------------------------------------------------
extern "C" void kernel_launch(void* const* d_in, const int* in_sizes, int n_in,
                              void* d_out, int out_size) {
    const float* X      = (const float*)d_in[0];
    const int*   labels = (const int*)d_in[1];
    float*       out    = (float*)d_out;

    fused_triplet_kernel<<<NBLK, 256>>>(X, labels, out);
}

// round 12
// speedup vs baseline: 1.7043x; 1.1960x over previous
#include <cuda_runtime.h>
#include <cuda_bf16.h>
#include <cstdint>

// Problem constants (fixed shapes from reference setup_inputs)
#define N 384
#define D 512
#define MARGIN 1.0f
#define NBLK 384
#define KSLICES 8
#define KS (D / KSLICES)          // 64 k per slice
#define TILES 6                   // 6x6 tiles of 64x64
#define LDT 68                    // smem tile row stride (floats): 4 mod 32 -> conflict-free frags

// Scratch: device globals (no allocation allowed)
__device__ float g_Gp[KSLICES][N * N];  // split-K Gram partials (tf32 mma, fp32 accum)
__device__ float g_sq[N];               // fp32 row sums of x*x
__device__ float g_asum[N];             // per-anchor triplet loss sum
__device__ int   g_acnt[N];             // per-anchor valid-triple count

// Sync state (integer only; epoch monotone across graph replays,
// count/ticket self-reset each launch -> deterministic, replay-safe)
__device__ unsigned g_count  = 0;
__device__ unsigned g_epoch  = 0;
__device__ unsigned g_ticket = 0;

__device__ __forceinline__ void grid_barrier() {
    __syncthreads();
    if (threadIdx.x == 0) {
        unsigned e = *(volatile unsigned*)&g_epoch;
        __threadfence();
        if (atomicAdd(&g_count, 1u) == NBLK - 1) {
            g_count = 0;
            __threadfence();
            *(volatile unsigned*)&g_epoch = e + 1;   // release
        } else {
            while (*(volatile unsigned*)&g_epoch == e) { __nanosleep(64); }
        }
        __threadfence();
    }
    __syncthreads();
}

// Round-to-nearest TF32 bit pattern (matches cuBLAS operand conversion; the
// fp32-vs-tf32 gram delta on the final loss was measured at ~1e-5 in R1/R4)
__device__ __forceinline__ uint32_t f2tf(float x) {
    uint32_t u;
    asm("cvt.rna.tf32.f32 %0, %1;" : "=r"(u) : "f"(x));
    return u;
}

__device__ __forceinline__ void mma_tf32(float c[4],
                                         uint32_t a0, uint32_t a1, uint32_t a2, uint32_t a3,
                                         uint32_t b0, uint32_t b1) {
    asm volatile(
        "mma.sync.aligned.m16n8k8.row.col.f32.tf32.tf32.f32 "
        "{%0,%1,%2,%3}, {%4,%5,%6,%7}, {%8,%9}, {%0,%1,%2,%3};"
        : "+f"(c[0]), "+f"(c[1]), "+f"(c[2]), "+f"(c[3])
        : "r"(a0), "r"(a1), "r"(a2), "r"(a3), "r"(b0), "r"(b1));
}

// ---------------------------------------------------------------------------
// Single fused kernel, 384 blocks x 256 threads, all co-resident
// (launch_bounds(256,3): 444 slots >= 384 -> grid barrier safe; smem 34.8KB*3 < 228KB).
//
// Phase 1:
//   blocks   0..287 : split-K Gram via tf32 mma.sync (m16n8k8). Whole 64x64/KS=64
//                     slice staged in smem once (1 sync), warps 4x2, each warp
//                     16x32 out: 8 k-steps x (12 conflict-free LDS.32 + 4 mma).
//   blocks 288..383 : g_sq rows (4 rows per block, fp32, deterministic)
// grid barrier
// Phase 2: block a = anchor a: distance row from fixed-order sum of the 8
//          partials, ballot compaction, hinge pair sum, tree reduce.
// Last-ticket block: deterministic final reduction + divide -> out[0]
// ---------------------------------------------------------------------------
__global__ void __launch_bounds__(256, 3)
fused_triplet_kernel(const float* __restrict__ X,
                     const int*   __restrict__ labels,
                     float*       __restrict__ out) {
    __shared__ float pool[2 * 64 * LDT];   // 8704 floats = 34816 B (phase union)
    __shared__ int   s_np, s_nn, s_last;

    const int b   = blockIdx.x;
    const int tid = threadIdx.x;

    // ---------------- Phase 1 ----------------
    if (b < KSLICES * 36) {
        uint32_t* As = (uint32_t*)pool;             // [64][LDT] tf32 bits
        uint32_t* Bs = (uint32_t*)pool + 64 * LDT;
        const int kslice = b / 36;
        const int t      = b % 36;
        const int row0 = (t / TILES) * 64;
        const int col0 = (t % TILES) * 64;
        const int kbase = kslice * KS;

        // Stage the whole 64x64 k-slice of A and B tiles (tf32-converted).
        // thread -> rows {lr, lr+32}, col chunks {kg*4, kg*4+32}
        const int lr = tid >> 3;          // 0..31
        const int kg = tid & 7;           // 0..7
#pragma unroll
        for (int rh = 0; rh < 2; rh++) {
            const int r = lr + rh * 32;
#pragma unroll
            for (int h = 0; h < 2; h++) {
                const int kcol = kg * 4 + h * 32;
                float4 va = *(const float4*)&X[(row0 + r) * D + kbase + kcol];
                float4 vb = *(const float4*)&X[(col0 + r) * D + kbase + kcol];
                uint4 ua = make_uint4(f2tf(va.x), f2tf(va.y), f2tf(va.z), f2tf(va.w));
                uint4 ub = make_uint4(f2tf(vb.x), f2tf(vb.y), f2tf(vb.z), f2tf(vb.w));
                *(uint4*)&As[r * LDT + kcol] = ua;    // STS.128, conflict-free
                *(uint4*)&Bs[r * LDT + kcol] = ub;
            }
        }
        __syncthreads();

        // Warp grid 4x2: warp computes 16 rows x 32 cols.
        const int warp = tid >> 5;
        const int lane = tid & 31;
        const int wm = warp >> 1;         // 0..3
        const int wn = warp & 1;          // 0..1
        const int g  = lane >> 2;         // 0..7
        const int tg = lane & 3;          // 0..3

        float c[4][4];
#pragma unroll
        for (int nf = 0; nf < 4; nf++)
#pragma unroll
            for (int i = 0; i < 4; i++) c[nf][i] = 0.f;

        const uint32_t* Ar0 = As + (wm * 16 + g) * LDT;
        const uint32_t* Ar1 = As + (wm * 16 + g + 8) * LDT;
        const uint32_t* Bq0 = Bs + (wn * 32 + g) * LDT;

#pragma unroll
        for (int ks = 0; ks < 8; ks++) {
            const int k0 = ks * 8;
            uint32_t a0 = Ar0[k0 + tg];
            uint32_t a1 = Ar1[k0 + tg];
            uint32_t a2 = Ar0[k0 + tg + 4];
            uint32_t a3 = Ar1[k0 + tg + 4];
#pragma unroll
            for (int nf = 0; nf < 4; nf++) {
                const uint32_t* Bq = Bq0 + nf * 8 * LDT;
                uint32_t b0 = Bq[k0 + tg];
                uint32_t b1 = Bq[k0 + tg + 4];
                mma_tf32(c[nf], a0, a1, a2, a3, b0, b1);
            }
        }

        float* Gp = g_Gp[kslice];
#pragma unroll
        for (int nf = 0; nf < 4; nf++) {
            const int ccol = col0 + wn * 32 + nf * 8 + 2 * tg;
            *(float2*)&Gp[(row0 + wm * 16 + g)     * N + ccol] = make_float2(c[nf][0], c[nf][1]);
            *(float2*)&Gp[(row0 + wm * 16 + g + 8) * N + ccol] = make_float2(c[nf][2], c[nf][3]);
        }
    } else {
        // Squared row norms: 4 rows per block, 64 threads each (fp32, fixed order)
        const int quad = tid >> 6;                 // 0..3
        const int lane = tid & 63;
        const int row  = (b - KSLICES * 36) * 4 + quad;
        const float* xr = X + row * D;
        float s = 0.0f;
#pragma unroll
        for (int i = 0; i < D / 64; i++) {
            float v = xr[lane + i * 64];
            s = fmaf(v, v, s);
        }
        float* red = pool + quad * 64;
        red[lane] = s;
        __syncthreads();
#pragma unroll
        for (int st = 32; st > 0; st >>= 1) {
            if (lane < st) red[lane] += red[lane + st];
            __syncthreads();
        }
        if (lane == 0) g_sq[row] = red[0];
    }

    grid_barrier();

    // ---------------- Phase 2: anchor = blockIdx.x ----------------
    {
        float* dr  = pool;            // [384]
        float* pd  = pool + 384;      // [384]
        float* nd  = pool + 768;      // [384]
        float* red = pool + 1152;     // [256]

        const int a = b;
        const float sqa = g_sq[a];
        const int la  = labels[a];

        // distance row: fixed-order split-K combine, then safe sqrt
        for (int j = tid; j < N; j += 256) {
            float g = g_Gp[0][a * N + j];
#pragma unroll
            for (int s = 1; s < KSLICES; s++) g += g_Gp[s][a * N + j];
            float d2 = sqa + g_sq[j] - 2.0f * g;
            dr[j] = sqrtf(fmaxf(d2, 0.0f));
        }
        __syncthreads();

        // warp 0: deterministic (index-ordered) compaction
        if (tid < 32) {
            int npos = 0, nneg = 0;
#pragma unroll
            for (int c = 0; c < N / 32; c++) {
                int j = c * 32 + tid;
                bool isp = (labels[j] == la);
                unsigned m = __ballot_sync(0xffffffffu, isp);
                int below_pos = __popc(m & ((1u << tid) - 1u));
                float d = dr[j];
                if (isp) pd[npos + below_pos] = d;
                else     nd[nneg + (tid - below_pos)] = d;
                int p = __popc(m);
                npos += p;
                nneg += 32 - p;
            }
            if (tid == 0) { s_np = npos; s_nn = nneg; }
        }
        __syncthreads();

        const int np = s_np;
        const int nn = s_nn;

        // hinge pair sum: p outer (broadcast LDS), n strided (sequential LDS)
        float acc = 0.0f;
        for (int p = 0; p < np; p++) {
            const float dpm = pd[p] + MARGIN;
            for (int n = tid; n < nn; n += 256)
                acc += fmaxf(dpm - nd[n], 0.0f);
        }
        red[tid] = acc;
        __syncthreads();
#pragma unroll
        for (int s = 128; s > 0; s >>= 1) {
            if (tid < s) red[tid] += red[tid + s];
            __syncthreads();
        }
        if (tid == 0) {
            g_asum[a] = red[0];
            g_acnt[a] = np * nn;
        }
    }

    // ---------------- Finalize: last block by ticket ----------------
    __syncthreads();
    if (tid == 0) {
        __threadfence();
        unsigned t = atomicAdd(&g_ticket, 1u);
        s_last = (t == NBLK - 1) ? 1 : 0;
    }
    __syncthreads();

    if (s_last) {
        if (tid == 0) g_ticket = 0;      // reset for next replay
        __threadfence();                  // acquire: see all g_asum/g_acnt

        float* rs = pool;                 // [256]
        int*   rc = (int*)(pool + 256);   // [256]
        float s = 0.0f;
        int   c = 0;
        for (int i = tid; i < N; i += 256) {  // fixed order -> deterministic
            s += g_asum[i];
            c += g_acnt[i];
        }
        rs[tid] = s;
        rc[tid] = c;
        __syncthreads();
#pragma unroll
        for (int st = 128; st > 0; st >>= 1) {
            if (tid < st) { rs[tid] += rs[tid + st]; rc[tid] += rc[tid + st]; }
            __syncthreads();
        }
        if (tid == 0) {
            out[0] = rs[0] / ((float)rc[0] + 1e-16f);
        }
    }
}

// ---------------------------------------------------------------------------
extern "C" void kernel_launch(void* const* d_in, const int* in_sizes, int n_in,
                              void* d_out, int out_size) {
    const float* X      = (const float*)d_in[0];
    const int*   labels = (const int*)d_in[1];
    float*       out    = (float*)d_out;

    fused_triplet_kernel<<<NBLK, 256>>>(X, labels, out);
}

// round 13
// speedup vs baseline: 1.7100x; 1.0033x over previous
#include <cuda_runtime.h>
#include <cuda_bf16.h>
#include <cstdint>

// Problem constants (fixed shapes from reference setup_inputs)
#define N 384
#define D 512
#define MARGIN 1.0f
#define KSLICES 8
#define KS (D / KSLICES)          // 64 k per slice
#define TILES 6                   // 6x6 tiles of 64x64
#define LDT 68                    // smem tile row stride (floats): 4 mod 32 -> conflict-free frags

// Scratch: device globals (no allocation allowed)
__device__ float g_Gp[KSLICES][N * N];  // split-K Gram partials (tf32 mma, fp32 accum)
__device__ float g_sq[N];               // fp32 row sums of x*x
__device__ float g_asum[N];             // per-anchor triplet loss sum
__device__ int   g_acnt[N];             // per-anchor valid-triple count

// Round-to-nearest TF32 bit pattern (matches cuBLAS operand conversion; the
// fp32-vs-tf32 gram delta on the final loss measured ~1e-5 in R1/R4 -> safe)
__device__ __forceinline__ uint32_t f2tf(float x) {
    uint32_t u;
    asm("cvt.rna.tf32.f32 %0, %1;" : "=r"(u) : "f"(x));
    return u;
}

__device__ __forceinline__ void mma_tf32(float c[4],
                                         uint32_t a0, uint32_t a1, uint32_t a2, uint32_t a3,
                                         uint32_t b0, uint32_t b1) {
    asm volatile(
        "mma.sync.aligned.m16n8k8.row.col.f32.tf32.tf32.f32 "
        "{%0,%1,%2,%3}, {%4,%5,%6,%7}, {%8,%9}, {%0,%1,%2,%3};"
        : "+f"(c[0]), "+f"(c[1]), "+f"(c[2]), "+f"(c[3])
        : "r"(a0), "r"(a1), "r"(a2), "r"(a3), "r"(b0), "r"(b1));
}

// ---------------------------------------------------------------------------
// Kernel A: blocks 0..287 split-K Gram via tf32 mma; blocks 288..383 g_sq.
// (graph-sequenced; no grid barrier, no co-residency requirement)
// ---------------------------------------------------------------------------
__global__ void __launch_bounds__(256)
gram_sq_kernel(const float* __restrict__ X) {
    __shared__ float pool[2 * 64 * LDT];   // 34816 B
    const int b   = blockIdx.x;
    const int tid = threadIdx.x;

    if (b < KSLICES * 36) {
        uint32_t* As = (uint32_t*)pool;             // [64][LDT] tf32 bits
        uint32_t* Bs = (uint32_t*)pool + 64 * LDT;
        const int kslice = b / 36;
        const int t      = b % 36;
        const int row0 = (t / TILES) * 64;
        const int col0 = (t % TILES) * 64;
        const int kbase = kslice * KS;

        // Stage the whole 64x64 k-slice of A and B tiles (tf32-converted).
        const int lr = tid >> 3;          // 0..31
        const int kg = tid & 7;           // 0..7
#pragma unroll
        for (int rh = 0; rh < 2; rh++) {
            const int r = lr + rh * 32;
#pragma unroll
            for (int h = 0; h < 2; h++) {
                const int kcol = kg * 4 + h * 32;
                float4 va = *(const float4*)&X[(row0 + r) * D + kbase + kcol];
                float4 vb = *(const float4*)&X[(col0 + r) * D + kbase + kcol];
                uint4 ua = make_uint4(f2tf(va.x), f2tf(va.y), f2tf(va.z), f2tf(va.w));
                uint4 ub = make_uint4(f2tf(vb.x), f2tf(vb.y), f2tf(vb.z), f2tf(vb.w));
                *(uint4*)&As[r * LDT + kcol] = ua;    // STS.128, conflict-free
                *(uint4*)&Bs[r * LDT + kcol] = ub;
            }
        }
        __syncthreads();

        // Warp grid 4x2: warp computes 16 rows x 32 cols.
        const int warp = tid >> 5;
        const int lane = tid & 31;
        const int wm = warp >> 1;         // 0..3
        const int wn = warp & 1;          // 0..1
        const int g  = lane >> 2;         // 0..7
        const int tg = lane & 3;          // 0..3

        float c[4][4];
#pragma unroll
        for (int nf = 0; nf < 4; nf++)
#pragma unroll
            for (int i = 0; i < 4; i++) c[nf][i] = 0.f;

        const uint32_t* Ar0 = As + (wm * 16 + g) * LDT;
        const uint32_t* Ar1 = As + (wm * 16 + g + 8) * LDT;
        const uint32_t* Bq0 = Bs + (wn * 32 + g) * LDT;

#pragma unroll
        for (int ks = 0; ks < 8; ks++) {
            const int k0 = ks * 8;
            uint32_t a0 = Ar0[k0 + tg];
            uint32_t a1 = Ar1[k0 + tg];
            uint32_t a2 = Ar0[k0 + tg + 4];
            uint32_t a3 = Ar1[k0 + tg + 4];
#pragma unroll
            for (int nf = 0; nf < 4; nf++) {
                const uint32_t* Bq = Bq0 + nf * 8 * LDT;
                uint32_t b0 = Bq[k0 + tg];
                uint32_t b1 = Bq[k0 + tg + 4];
                mma_tf32(c[nf], a0, a1, a2, a3, b0, b1);
            }
        }

        float* Gp = g_Gp[kslice];
#pragma unroll
        for (int nf = 0; nf < 4; nf++) {
            const int ccol = col0 + wn * 32 + nf * 8 + 2 * tg;
            *(float2*)&Gp[(row0 + wm * 16 + g)     * N + ccol] = make_float2(c[nf][0], c[nf][1]);
            *(float2*)&Gp[(row0 + wm * 16 + g + 8) * N + ccol] = make_float2(c[nf][2], c[nf][3]);
        }
    } else {
        // Squared row norms: 4 rows per block, 64 threads each (fp32, fixed order)
        const int quad = tid >> 6;                 // 0..3
        const int lane = tid & 63;
        const int row  = (b - KSLICES * 36) * 4 + quad;
        const float* xr = X + row * D;
        float s = 0.0f;
#pragma unroll
        for (int i = 0; i < D / 64; i++) {
            float v = xr[lane + i * 64];
            s = fmaf(v, v, s);
        }
        float* red = pool + quad * 64;
        red[lane] = s;
        __syncthreads();
#pragma unroll
        for (int st = 32; st > 0; st >>= 1) {
            if (lane < st) red[lane] += red[lane + st];
            __syncthreads();
        }
        if (lane == 0) g_sq[row] = red[0];
    }
}

// ---------------------------------------------------------------------------
// Kernel B: one block per anchor a.
//  - labels staged to smem (LDS instead of L2 in the serial compaction loop)
//  - distance row from fixed-order split-K combine + safe sqrt
//  - warp-0 ballot compaction (deterministic, index-ordered)
//  - hinge pair sum; warp-shuffle reduce (1 block barrier total in reduce)
// ---------------------------------------------------------------------------
__global__ void __launch_bounds__(256)
triplet_kernel(const int* __restrict__ labels) {
    __shared__ float dr[N];
    __shared__ float pd[N];
    __shared__ float nd[N];
    __shared__ int   lab[N];
    __shared__ float red[8];
    __shared__ int   s_np, s_nn;

    const int a   = blockIdx.x;
    const int tid = threadIdx.x;
    const int warp = tid >> 5;
    const int lane = tid & 31;

    // stage labels
    for (int j = tid; j < N; j += 256) lab[j] = labels[j];

    // distance row: fixed-order split-K combine, then safe sqrt
    const float sqa = g_sq[a];
    for (int j = tid; j < N; j += 256) {
        float g = g_Gp[0][a * N + j];
#pragma unroll
        for (int s = 1; s < KSLICES; s++) g += g_Gp[s][a * N + j];
        float d2 = sqa + g_sq[j] - 2.0f * g;
        dr[j] = sqrtf(fmaxf(d2, 0.0f));
    }
    __syncthreads();

    // warp 0: deterministic (index-ordered) compaction from smem labels
    if (warp == 0) {
        const int la = lab[a];
        int npos = 0, nneg = 0;
#pragma unroll
        for (int c = 0; c < N / 32; c++) {
            int j = c * 32 + lane;
            bool isp = (lab[j] == la);
            unsigned m = __ballot_sync(0xffffffffu, isp);
            int below_pos = __popc(m & ((1u << lane) - 1u));
            float d = dr[j];
            if (isp) pd[npos + below_pos] = d;
            else     nd[nneg + (lane - below_pos)] = d;
            int p = __popc(m);
            npos += p;
            nneg += 32 - p;
        }
        if (lane == 0) { s_np = npos; s_nn = nneg; }
    }
    __syncthreads();

    const int np = s_np;
    const int nn = s_nn;

    // hinge pair sum: p outer (broadcast LDS), n strided (sequential LDS)
    float acc = 0.0f;
    for (int p = 0; p < np; p++) {
        const float dpm = pd[p] + MARGIN;
        for (int n = tid; n < nn; n += 256)
            acc += fmaxf(dpm - nd[n], 0.0f);
    }

    // warp-shuffle reduce (fixed order -> deterministic)
#pragma unroll
    for (int o = 16; o > 0; o >>= 1)
        acc += __shfl_down_sync(0xffffffffu, acc, o);
    if (lane == 0) red[warp] = acc;
    __syncthreads();
    if (tid == 0) {
        float s = ((red[0] + red[1]) + (red[2] + red[3]))
                + ((red[4] + red[5]) + (red[6] + red[7]));
        g_asum[a] = s;
        g_acnt[a] = np * nn;
    }
}

// ---------------------------------------------------------------------------
// Kernel C: deterministic reduction of per-anchor partials + final divide.
// ---------------------------------------------------------------------------
__global__ void __launch_bounds__(128)
finalize_kernel(float* __restrict__ out) {
    const int tid = threadIdx.x;         // 128 threads
    __shared__ float rs[128];
    __shared__ int   rc[128];

    float s = 0.0f;
    int   c = 0;
    for (int i = tid; i < N; i += 128) {
        s += g_asum[i];
        c += g_acnt[i];
    }
    rs[tid] = s;
    rc[tid] = c;
    __syncthreads();

#pragma unroll
    for (int st = 64; st > 0; st >>= 1) {
        if (tid < st) { rs[tid] += rs[tid + st]; rc[tid] += rc[tid + st]; }
        __syncthreads();
    }

    if (tid == 0) {
        out[0] = rs[0] / ((float)rc[0] + 1e-16f);
    }
}

// ---------------------------------------------------------------------------
extern "C" void kernel_launch(void* const* d_in, const int* in_sizes, int n_in,
                              void* d_out, int out_size) {
    const float* X      = (const float*)d_in[0];
    const int*   labels = (const int*)d_in[1];
    float*       out    = (float*)d_out;

    gram_sq_kernel<<<KSLICES * 36 + 96, 256>>>(X);
    triplet_kernel<<<N, 256>>>(labels);
    finalize_kernel<<<1, 128>>>(out);
}

// round 15
// speedup vs baseline: 1.9432x; 1.1364x over previous
#include <cuda_runtime.h>
#include <cuda_bf16.h>
#include <cstdint>

// Problem constants (fixed shapes from reference setup_inputs)
#define N 384
#define D 512
#define MARGIN 1.0f
#define KSLICES 4
#define KS (D / KSLICES)          // 128 k per slice (2 chunks of 64)
#define TILES 6                   // 6x6 tiles of 64x64
#define LDT 68                    // smem tile row stride (floats): 4 mod 32 -> conflict-free frags

// Scratch: device globals (no allocation allowed)
__device__ float g_Gp[KSLICES][N * N];  // split-K Gram partials (tf32 mma, fp32 accum)
__device__ float g_sq[N];               // fp32 row sums of x*x
__device__ float g_asum[N];             // per-anchor triplet loss sum
__device__ int   g_acnt[N];             // per-anchor valid-triple count
__device__ unsigned g_ticket = 0;       // finalize ticket (self-resetting)

// Round-to-nearest TF32 (matches cuBLAS; fp32-vs-tf32 loss delta ~1e-5, safe)
__device__ __forceinline__ uint32_t f2tf(float x) {
    uint32_t u;
    asm("cvt.rna.tf32.f32 %0, %1;" : "=r"(u) : "f"(x));
    return u;
}

__device__ __forceinline__ void mma_tf32(float c[4],
                                         uint32_t a0, uint32_t a1, uint32_t a2, uint32_t a3,
                                         uint32_t b0, uint32_t b1) {
    asm volatile(
        "mma.sync.aligned.m16n8k8.row.col.f32.tf32.tf32.f32 "
        "{%0,%1,%2,%3}, {%4,%5,%6,%7}, {%8,%9}, {%0,%1,%2,%3};"
        : "+f"(c[0]), "+f"(c[1]), "+f"(c[2]), "+f"(c[3])
        : "r"(a0), "r"(a1), "r"(a2), "r"(a3), "r"(b0), "r"(b1));
}

// ---------------------------------------------------------------------------
// Kernel A: blocks 0..143 split-K Gram (KS=128, 2 chunks of 64, register
// double-buffered LDG so chunk-1 loads overlap chunk-0 mma);
// blocks 144..239 g_sq (4 rows per block).
// ---------------------------------------------------------------------------
__global__ void __launch_bounds__(256)
gram_sq_kernel(const float* __restrict__ X) {
    __shared__ float pool[2 * 64 * LDT];   // 34816 B
    const int b   = blockIdx.x;
    const int tid = threadIdx.x;

    if (b < KSLICES * 36) {
        uint32_t* As = (uint32_t*)pool;             // [64][LDT] tf32 bits
        uint32_t* Bs = (uint32_t*)pool + 64 * LDT;
        const int kslice = b / 36;
        const int t      = b % 36;
        const int row0 = (t / TILES) * 64;
        const int col0 = (t % TILES) * 64;
        const int kbase = kslice * KS;

        const int lr = tid >> 3;          // 0..31
        const int kg = tid & 7;           // 0..7

        // prefetch chunk 0 (8 independent float4 LDG)
        float4 pva[2][2], pvb[2][2];
#pragma unroll
        for (int rh = 0; rh < 2; rh++) {
            const int r = lr + rh * 32;
#pragma unroll
            for (int h = 0; h < 2; h++) {
                const int kcol = kg * 4 + h * 32;
                pva[rh][h] = *(const float4*)&X[(row0 + r) * D + kbase + kcol];
                pvb[rh][h] = *(const float4*)&X[(col0 + r) * D + kbase + kcol];
            }
        }

        const int warp = tid >> 5;
        const int lane = tid & 31;
        const int wm = warp >> 1;         // 0..3
        const int wn = warp & 1;          // 0..1
        const int g  = lane >> 2;         // 0..7
        const int tg = lane & 3;          // 0..3

        float c[4][4];
#pragma unroll
        for (int nf = 0; nf < 4; nf++)
#pragma unroll
            for (int i = 0; i < 4; i++) c[nf][i] = 0.f;

        const uint32_t* Ar0 = As + (wm * 16 + g) * LDT;
        const uint32_t* Ar1 = As + (wm * 16 + g + 8) * LDT;
        const uint32_t* Bq0 = Bs + (wn * 32 + g) * LDT;

#pragma unroll
        for (int ch = 0; ch < 2; ch++) {              // 2 chunks of 64 k
            // store prefetched chunk to smem (tf32-converted)
#pragma unroll
            for (int rh = 0; rh < 2; rh++) {
                const int r = lr + rh * 32;
#pragma unroll
                for (int h = 0; h < 2; h++) {
                    const int kcol = kg * 4 + h * 32;
                    float4 va = pva[rh][h], vb = pvb[rh][h];
                    *(uint4*)&As[r * LDT + kcol] =
                        make_uint4(f2tf(va.x), f2tf(va.y), f2tf(va.z), f2tf(va.w));
                    *(uint4*)&Bs[r * LDT + kcol] =
                        make_uint4(f2tf(vb.x), f2tf(vb.y), f2tf(vb.z), f2tf(vb.w));
                }
            }
            __syncthreads();

            // prefetch next chunk while mma runs
            if (ch == 0) {
                const int kb1 = kbase + 64;
#pragma unroll
                for (int rh = 0; rh < 2; rh++) {
                    const int r = lr + rh * 32;
#pragma unroll
                    for (int h = 0; h < 2; h++) {
                        const int kcol = kg * 4 + h * 32;
                        pva[rh][h] = *(const float4*)&X[(row0 + r) * D + kb1 + kcol];
                        pvb[rh][h] = *(const float4*)&X[(col0 + r) * D + kb1 + kcol];
                    }
                }
            }

#pragma unroll
            for (int ks = 0; ks < 8; ks++) {
                const int k0 = ks * 8;
                uint32_t a0 = Ar0[k0 + tg];
                uint32_t a1 = Ar1[k0 + tg];
                uint32_t a2 = Ar0[k0 + tg + 4];
                uint32_t a3 = Ar1[k0 + tg + 4];
#pragma unroll
                for (int nf = 0; nf < 4; nf++) {
                    const uint32_t* Bq = Bq0 + nf * 8 * LDT;
                    uint32_t b0 = Bq[k0 + tg];
                    uint32_t b1 = Bq[k0 + tg + 4];
                    mma_tf32(c[nf], a0, a1, a2, a3, b0, b1);
                }
            }
            if (ch == 0) __syncthreads();
        }

        float* Gp = g_Gp[kslice];
#pragma unroll
        for (int nf = 0; nf < 4; nf++) {
            const int ccol = col0 + wn * 32 + nf * 8 + 2 * tg;
            *(float2*)&Gp[(row0 + wm * 16 + g)     * N + ccol] = make_float2(c[nf][0], c[nf][1]);
            *(float2*)&Gp[(row0 + wm * 16 + g + 8) * N + ccol] = make_float2(c[nf][2], c[nf][3]);
        }
    } else {
        // Squared row norms: 4 rows per block, 64 threads each (fp32, fixed order)
        const int quad = tid >> 6;                 // 0..3
        const int lane = tid & 63;
        const int row  = (b - KSLICES * 36) * 4 + quad;
        const float* xr = X + row * D;
        float s = 0.0f;
#pragma unroll
        for (int i = 0; i < D / 64; i++) {
            float v = xr[lane + i * 64];
            s = fmaf(v, v, s);
        }
        float* red = pool + quad * 64;
        red[lane] = s;
        __syncthreads();
#pragma unroll
        for (int st = 32; st > 0; st >>= 1) {
            if (lane < st) red[lane] += red[lane + st];
            __syncthreads();
        }
        if (lane == 0) g_sq[row] = red[0];
    }
}

// ---------------------------------------------------------------------------
// Kernel B: one block per anchor a; last-ticket block also finalizes.
//  - labels staged to smem
//  - distance row from fixed-order 4-way split-K combine + safe sqrt
//  - warp-0 ballot compaction (deterministic, index-ordered)
//  - hinge pair sum; warp-shuffle reduce
//  - ticketed finalize: fixed-order reduce of g_asum/g_acnt -> out[0]
// ---------------------------------------------------------------------------
__global__ void __launch_bounds__(256)
triplet_kernel(const int* __restrict__ labels, float* __restrict__ out) {
    __shared__ float dr[N];
    __shared__ float pd[N];
    __shared__ float nd[N];
    __shared__ int   lab[N];
    __shared__ float red[8];
    __shared__ int   s_np, s_nn, s_last;

    const int a   = blockIdx.x;
    const int tid = threadIdx.x;
    const int warp = tid >> 5;
    const int lane = tid & 31;

    // stage labels
    for (int j = tid; j < N; j += 256) lab[j] = labels[j];

    // distance row: fixed-order split-K combine, then safe sqrt
    const float sqa = g_sq[a];
    for (int j = tid; j < N; j += 256) {
        float g = (g_Gp[0][a * N + j] + g_Gp[1][a * N + j])
                + (g_Gp[2][a * N + j] + g_Gp[3][a * N + j]);
        float d2 = sqa + g_sq[j] - 2.0f * g;
        dr[j] = sqrtf(fmaxf(d2, 0.0f));
    }
    __syncthreads();

    // warp 0: deterministic (index-ordered) compaction from smem labels
    if (warp == 0) {
        const int la = lab[a];
        int npos = 0, nneg = 0;
#pragma unroll
        for (int c = 0; c < N / 32; c++) {
            int j = c * 32 + lane;
            bool isp = (lab[j] == la);
            unsigned m = __ballot_sync(0xffffffffu, isp);
            int below_pos = __popc(m & ((1u << lane) - 1u));
            float d = dr[j];
            if (isp) pd[npos + below_pos] = d;
            else     nd[nneg + (lane - below_pos)] = d;
            int p = __popc(m);
            npos += p;
            nneg += 32 - p;
        }
        if (lane == 0) { s_np = npos; s_nn = nneg; }
    }
    __syncthreads();

    const int np = s_np;
    const int nn = s_nn;

    // hinge pair sum: p outer (broadcast LDS), n strided (sequential LDS)
    float acc = 0.0f;
    for (int p = 0; p < np; p++) {
        const float dpm = pd[p] + MARGIN;
        for (int n = tid; n < nn; n += 256)
            acc += fmaxf(dpm - nd[n], 0.0f);
    }

    // warp-shuffle reduce (fixed order -> deterministic)
#pragma unroll
    for (int o = 16; o > 0; o >>= 1)
        acc += __shfl_down_sync(0xffffffffu, acc, o);
    if (lane == 0) red[warp] = acc;
    __syncthreads();
    if (tid == 0) {
        float s = ((red[0] + red[1]) + (red[2] + red[3]))
                + ((red[4] + red[5]) + (red[6] + red[7]));
        g_asum[a] = s;
        g_acnt[a] = np * nn;
    }

    // ---------------- ticketed finalize (last block) ----------------
    __syncthreads();
    if (tid == 0) {
        __threadfence();
        unsigned t = atomicAdd(&g_ticket, 1u);
        s_last = (t == N - 1) ? 1 : 0;
    }
    __syncthreads();

    if (s_last) {
        if (tid == 0) g_ticket = 0;      // reset for next replay
        __threadfence();                  // acquire: see all g_asum/g_acnt

        float* rs = dr;                   // reuse smem
        int*   rc = (int*)pd;
        float s = 0.0f;
        int   c = 0;
        for (int i = tid; i < N; i += 256) {  // fixed order -> deterministic
            s += g_asum[i];
            c += g_acnt[i];
        }
        rs[tid] = s;
        rc[tid] = c;
        __syncthreads();
#pragma unroll
        for (int st = 128; st > 0; st >>= 1) {
            if (tid < st) { rs[tid] += rs[tid + st]; rc[tid] += rc[tid + st]; }
            __syncthreads();
        }
        if (tid == 0) {
            out[0] = rs[0] / ((float)rc[0] + 1e-16f);
        }
    }
}

// ---------------------------------------------------------------------------
extern "C" void kernel_launch(void* const* d_in, const int* in_sizes, int n_in,
                              void* d_out, int out_size) {
    const float* X      = (const float*)d_in[0];
    const int*   labels = (const int*)d_in[1];
    float*       out    = (float*)d_out;

    gram_sq_kernel<<<KSLICES * 36 + 96, 256>>>(X);
    triplet_kernel<<<N, 256>>>(labels, out);
}